// round 5
// baseline (speedup 1.0000x reference)
#include <cuda_runtime.h>

#define Bv 8
#define Tv 1000
#define Dv 1024
#define NCHUNK 74   // 4 blocks/SM at grid (74,8) on 148 SMs

// Scratch (__device__ globals per allocation rules)
__device__ float g_part[NCHUNK * 8 * 1024];  // per-chunk partial t-sums
__device__ float g_vsump[4 * 8 * 64];        // 4 j-block partials of vsum
__device__ float g_row[8 * 1024];            // per-batch output row

// ---------------------------------------------------------------------------
// 1) Partial sums over t. grid (74, 8), 256 threads, one float4 col-slice per
//    thread. Balanced chunks of 13-14 rows; 592 blocks = exactly 4 per SM.
// ---------------------------------------------------------------------------
__global__ void __launch_bounds__(256)
xsum_part_kernel(const float* __restrict__ x)
{
    const int chunk = blockIdx.x;                 // 0..73
    const int b     = blockIdx.y;                 // 0..7
    const int t0    = (chunk * Tv) / NCHUNK;
    const int t1    = ((chunk + 1) * Tv) / NCHUNK;
    const int j4    = threadIdx.x << 2;

    const float4* xp = (const float4*)(x + ((size_t)b * Tv + t0) * Dv + j4);
    float4 acc = make_float4(0.f, 0.f, 0.f, 0.f);
    const int rows = t1 - t0;
    #pragma unroll 7
    for (int tt = 0; tt < rows; tt++) {
        float4 v = xp[(size_t)tt * (Dv / 4)];
        acc.x += v.x; acc.y += v.y; acc.z += v.z; acc.w += v.w;
    }
    *(float4*)(g_part + ((size_t)(chunk * 8 + b)) * Dv + j4) = acc;
}

// ---------------------------------------------------------------------------
// 2) vsum partials: grid (8 b, 4 jblk). Reduce the 74 chunk-partials over this
//    256-wide j slice, then GEMV vs Wv -> g_vsump[jblk][b][64].
// ---------------------------------------------------------------------------
__global__ void __launch_bounds__(256)
vsum_part_kernel(const float* __restrict__ Wv)
{
    __shared__ float xs[256];
    __shared__ float p[4][64];
    const int b    = blockIdx.x;
    const int jblk = blockIdx.y;
    const int tid  = threadIdx.x;
    const int jg   = jblk * 256;

    {
        float s = 0.f;
        #pragma unroll 8
        for (int c = 0; c < NCHUNK; c++)
            s += g_part[((size_t)(c * 8 + b)) * Dv + jg + tid];
        xs[tid] = s;
    }
    __syncthreads();

    const int d   = tid & 63;
    const int sub = tid >> 6;
    float acc = 0.f;
    #pragma unroll 16
    for (int jj = 0; jj < 64; jj++) {
        int j = sub * 64 + jj;
        acc += xs[j] * Wv[(size_t)(jg + j) * 64 + d];
    }
    p[sub][d] = acc;
    __syncthreads();
    if (tid < 64)
        g_vsump[(jblk * 8 + b) * 64 + tid] =
            p[0][tid] + p[1][tid] + p[2][tid] + p[3][tid];
}

// ---------------------------------------------------------------------------
// 3) row[b,n] = bo[n] + sum_m vs[b, m&63] * Wo[m, n].  grid 32 (32 cols each),
//    256 threads; warp w covers m in [w*128, w*128+128) with the two 64-aligned
//    halves folded (same d); cross-warp reduce in smem -> g_row.
// ---------------------------------------------------------------------------
__global__ void __launch_bounds__(256)
row_kernel(const float* __restrict__ Wo, const float* __restrict__ bv,
           const float* __restrict__ bo)
{
    __shared__ float vs[8 * 64];
    __shared__ float part[8][8][32];

    const int n0   = blockIdx.x * 32;
    const int tid  = threadIdx.x;
    const int lane = tid & 31;
    const int wid  = tid >> 5;
    const int n    = n0 + lane;

    #pragma unroll
    for (int i = tid; i < 512; i += 256) {
        int d = i & 63;
        float s = (float)Tv * bv[d];
        #pragma unroll
        for (int jb = 0; jb < 4; jb++)
            s += g_vsump[jb * 512 + i];
        vs[i] = s;
    }
    __syncthreads();

    float acc[8] = {};
    const int mbase = wid * 128;
    #pragma unroll 8
    for (int mm = 0; mm < 64; mm++) {
        float w1 = Wo[(size_t)(mbase + mm) * Dv + n];
        float w2 = Wo[(size_t)(mbase + mm + 64) * Dv + n];
        float w  = w1 + w2;
        #pragma unroll
        for (int b = 0; b < 8; b++)
            acc[b] = fmaf(vs[b * 64 + mm], w, acc[b]);
    }
    #pragma unroll
    for (int b = 0; b < 8; b++)
        part[wid][b][lane] = acc[b];
    __syncthreads();

    {
        int b = wid;
        float s = bo[n];
        #pragma unroll
        for (int w = 0; w < 8; w++)
            s += part[w][b][lane];
        g_row[b * Dv + n] = s;
    }
}

// ---------------------------------------------------------------------------
// 4) Broadcast: grid (74, 8), 256 threads. Block loads its batch row ONCE into
//    registers (one float4/thread) and streams 13-14 rows of STG.128.
// ---------------------------------------------------------------------------
__global__ void __launch_bounds__(256)
bcast_kernel(float* __restrict__ out)
{
    const int chunk = blockIdx.x;
    const int b     = blockIdx.y;
    const int t0    = (chunk * Tv) / NCHUNK;
    const int t1    = ((chunk + 1) * Tv) / NCHUNK;

    float4 v = ((const float4*)g_row)[b * 256 + threadIdx.x];
    float4* op = (float4*)out + ((size_t)b * Tv + t0) * 256 + threadIdx.x;
    #pragma unroll 7
    for (int t = 0; t < t1 - t0; t++)
        op[(size_t)t * 256] = v;
}

// ---------------------------------------------------------------------------
extern "C" void kernel_launch(void* const* d_in, const int* in_sizes, int n_in,
                              void* d_out, int out_size)
{
    const float* x  = (const float*)d_in[0];
    const float* Wv = (const float*)d_in[5];
    const float* bv = (const float*)d_in[6];
    const float* Wo = (const float*)d_in[7];
    const float* bo = (const float*)d_in[8];
    float* out = (float*)d_out;

    xsum_part_kernel<<<dim3(NCHUNK, 8), 256>>>(x);
    vsum_part_kernel<<<dim3(8, 4), 256>>>(Wv);
    row_kernel<<<32, 256>>>(Wo, bv, bo);
    bcast_kernel<<<dim3(NCHUNK, 8), 256>>>(out);
}